// round 2
// baseline (speedup 1.0000x reference)
#include <cuda_runtime.h>
#include <math.h>
#include <stdint.h>

#define SS   64
#define CC   32
#define CIN  3
#define HH   256
#define WW   256
#define WF   129

__device__ float  g_x1[(size_t)SS*CC*HH*WW];          // conv1 output (relu)
__device__ float  g_x2[(size_t)SS*CC*HH*WW];          // conv2+LRN+coswin
__device__ float2 g_zf[(size_t)SS*CC*WF*HH];          // row-rfft, layout [s][c][k][h]
__device__ float2 g_ghat[(size_t)SS*WF*HH];           // after ifft along H, [s][k][h]
__device__ float2 g_wft[(size_t)WF*CC*HH];            // wf transposed [k][c][hf]
__device__ float2 g_tw[256];                          // e^{-2pi i m/256}

__device__ __forceinline__ int swz(int i){ return i + (i>>4); }
#define SLICE 272

__device__ __forceinline__ float2 cmul(float2 a, float2 b){
    return make_float2(a.x*b.x - a.y*b.y, a.x*b.y + a.y*b.x);
}

// Radix-4 Stockham FFT-256 on shared memory (64 working threads per slice).
// Natural-order in and out. INV=true: conjugate twiddles, +i butterfly (no 1/N).
template<bool INV>
__device__ void fft256(float2* A, const float2* tw, int t, bool active){
    #pragma unroll
    for (int L = 1; L <= 64; L *= 4) {
        float2 X0, X1, X2, X3;
        int base = 0;
        if (active) {
            int k = t & (L-1);
            float2 x0 = A[swz(t)];
            float2 x1 = A[swz(t+64)];
            float2 x2 = A[swz(t+128)];
            float2 x3 = A[swz(t+192)];
            int tm = k * (64 / L);
            float2 w1 = tw[tm];
            float2 w2 = tw[(2*tm) & 255];
            float2 w3 = tw[(3*tm) & 255];
            if (INV){ w1.y = -w1.y; w2.y = -w2.y; w3.y = -w3.y; }
            x1 = cmul(x1, w1); x2 = cmul(x2, w2); x3 = cmul(x3, w3);
            float2 y0 = make_float2(x0.x+x2.x, x0.y+x2.y);
            float2 y1 = make_float2(x0.x-x2.x, x0.y-x2.y);
            float2 y2 = make_float2(x1.x+x3.x, x1.y+x3.y);
            float2 d  = make_float2(x1.x-x3.x, x1.y-x3.y);
            float2 y3 = INV ? make_float2(-d.y,  d.x)
                            : make_float2( d.y, -d.x);
            X0 = make_float2(y0.x+y2.x, y0.y+y2.y);
            X1 = make_float2(y1.x+y3.x, y1.y+y3.y);
            X2 = make_float2(y0.x-y2.x, y0.y-y2.y);
            X3 = make_float2(y1.x-y3.x, y1.y-y3.y);
            base = (t - k)*4 + k;
        }
        __syncthreads();
        if (active) {
            A[swz(base      )] = X0;
            A[swz(base +   L)] = X1;
            A[swz(base + 2*L)] = X2;
            A[swz(base + 3*L)] = X3;
        }
        __syncthreads();
    }
}

// ---------------- init: twiddle table + wf transpose ----------------
__global__ void k_init(const float* __restrict__ wf){
    int tid = blockIdx.x * blockDim.x + threadIdx.x;
    if (tid < 256) {
        double ang = -6.283185307179586476925286766559 * (double)tid / 256.0;
        g_tw[tid] = make_float2((float)cos(ang), (float)sin(ang));
    }
    int total = WF*CC*HH;
    for (int i = tid; i < total; i += gridDim.x * blockDim.x) {
        int hf = i & 255;
        int c  = (i >> 8) & 31;
        int k  = i >> 13;
        const float* p = wf + (((size_t)c*HH + hf)*WF + k)*2;
        g_wft[i] = make_float2(p[0], p[1]);
    }
}

// ---------------- conv1 + relu ----------------
__global__ void k_conv1(const float* __restrict__ z, const float* __restrict__ w1,
                        const float* __restrict__ b1){
    __shared__ float sIn[3*10*34];
    __shared__ float sW[27*32];
    int s  = blockIdx.z;
    int w0 = blockIdx.x * 32, h0 = blockIdx.y * 8;
    int tid = threadIdx.x;

    for (int i = tid; i < 27*32; i += 256)
        sW[i] = w1[(size_t)(i & 31)*27 + (i >> 5)];
    for (int i = tid; i < 3*10*34; i += 256) {
        int ci = i / 340, rem = i % 340, rr = rem / 34, cc = rem % 34;
        int gh = h0 + rr - 1, gw = w0 + cc - 1;
        float v = 0.f;
        if (gh >= 0 && gh < HH && gw >= 0 && gw < WW)
            v = z[(((size_t)s*CIN + ci)*HH + gh)*WW + gw];
        sIn[i] = v;
    }
    __syncthreads();

    int wg = tid & 7, r = (tid >> 3) & 7, cob = tid >> 6;
    int co0 = cob * 8;
    float acc[4][8];
    #pragma unroll
    for (int i = 0; i < 4; i++)
        #pragma unroll
        for (int j = 0; j < 8; j++) acc[i][j] = b1[co0 + j];

    #pragma unroll
    for (int ci = 0; ci < 3; ci++)
      #pragma unroll
      for (int kh = 0; kh < 3; kh++) {
        const float* rowp = &sIn[(ci*10 + r + kh)*34];
        #pragma unroll
        for (int kw = 0; kw < 3; kw++) {
            float x0 = rowp[wg      + kw];
            float x1 = rowp[wg + 8  + kw];
            float x2 = rowp[wg + 16 + kw];
            float x3 = rowp[wg + 24 + kw];
            const float* wp = &sW[((ci*3 + kh)*3 + kw)*32 + co0];
            #pragma unroll
            for (int j = 0; j < 8; j++) {
                float wv = wp[j];
                acc[0][j] += x0*wv; acc[1][j] += x1*wv;
                acc[2][j] += x2*wv; acc[3][j] += x3*wv;
            }
        }
      }

    int hh = h0 + r;
    #pragma unroll
    for (int i = 0; i < 4; i++) {
        int ww = w0 + wg + 8*i;
        #pragma unroll
        for (int j = 0; j < 8; j++) {
            float v = acc[i][j];
            v = v > 0.f ? v : 0.f;
            g_x1[(((size_t)s*CC + co0 + j)*HH + hh)*WW + ww] = v;
        }
    }
}

// ---------------- conv2 + bias + LRN + cos window ----------------
__global__ void k_conv2(const float* __restrict__ w2, const float* __restrict__ b2,
                        const float* __restrict__ coswin){
    extern __shared__ float sm[];
    float* sIn  = sm;                // 32*10*34 = 10880
    float* sW   = sm + 10880;        // 288*32   = 9216
    float* sOut = sW + 9216;         // 32*256   = 8192
    int s  = blockIdx.z;
    int w0 = blockIdx.x * 32, h0 = blockIdx.y * 8;
    int tid = threadIdx.x;

    for (int i = tid; i < 288*32; i += 256)
        sW[i] = w2[(size_t)(i & 31)*288 + (i >> 5)];
    for (int i = tid; i < 32*10*34; i += 256) {
        int ci = i / 340, rem = i % 340, rr = rem / 34, cc = rem % 34;
        int gh = h0 + rr - 1, gw = w0 + cc - 1;
        float v = 0.f;
        if (gh >= 0 && gh < HH && gw >= 0 && gw < WW)
            v = g_x1[(((size_t)s*CC + ci)*HH + gh)*WW + gw];
        sIn[i] = v;
    }
    __syncthreads();

    int wg = tid & 7, r = (tid >> 3) & 7, cob = tid >> 6;
    int co0 = cob * 8;
    float acc[4][8];
    #pragma unroll
    for (int i = 0; i < 4; i++)
        #pragma unroll
        for (int j = 0; j < 8; j++) acc[i][j] = b2[co0 + j];

    for (int ci = 0; ci < 32; ci++)
      #pragma unroll
      for (int kh = 0; kh < 3; kh++) {
        const float* rowp = &sIn[(ci*10 + r + kh)*34];
        #pragma unroll
        for (int kw = 0; kw < 3; kw++) {
            float x0 = rowp[wg      + kw];
            float x1 = rowp[wg + 8  + kw];
            float x2 = rowp[wg + 16 + kw];
            float x3 = rowp[wg + 24 + kw];
            const float* wp = &sW[((ci*3 + kh)*3 + kw)*32 + co0];
            #pragma unroll
            for (int j = 0; j < 8; j++) {
                float wv = wp[j];
                acc[0][j] += x0*wv; acc[1][j] += x1*wv;
                acc[2][j] += x2*wv; acc[3][j] += x3*wv;
            }
        }
      }

    #pragma unroll
    for (int i = 0; i < 4; i++) {
        int px = r*32 + wg + 8*i;
        #pragma unroll
        for (int j = 0; j < 8; j++) sOut[(co0 + j)*256 + px] = acc[i][j];
    }
    __syncthreads();

    // LRN per pixel (clipped window of 5 over channels) + cos window
    int px = tid;
    int rr = px >> 5, cc = px & 31;
    float yv[32];
    #pragma unroll
    for (int c = 0; c < 32; c++) yv[c] = sOut[c*256 + px];
    float cw = coswin[(size_t)(h0 + rr)*WW + (w0 + cc)];
    float win = yv[0]*yv[0] + yv[1]*yv[1] + yv[2]*yv[2];
    size_t obase = ((size_t)s*CC*HH + (size_t)(h0 + rr))*WW + (w0 + cc);
    #pragma unroll
    for (int c = 0; c < 32; c++) {
        float t = 1.0f + 2e-5f * win;               // k + (alpha/n)*win
        float v = yv[c] * __powf(t, -0.75f) * cw;
        g_x2[obase + (size_t)c*HH*WW] = v;
        if (c + 3 < 32) win += yv[c+3]*yv[c+3];
        if (c - 2 >= 0) win -= yv[c-2]*yv[c-2];
    }
}

// ---------------- stage A: row rfft (2 rows packed), transposed store ----------------
__global__ void k_fftrow(){
    __shared__ float2 buf[8*SLICE];
    __shared__ float2 stw[256];
    int tid = threadIdx.x;               // 512
    int sc  = blockIdx.y;                // s*32 + c
    int h0  = blockIdx.x * 16;
    if (tid < 256) stw[tid] = g_tw[tid];

    const float* src = g_x2 + (size_t)sc*HH*WW + (size_t)h0*WW;
    for (int i = tid; i < 16*256; i += 512) {
        int row = i >> 8, j = i & 255;
        float v = src[(size_t)row*WW + j];
        float* dst = (float*)&buf[(row>>1)*SLICE + swz(j)];
        dst[row & 1] = v;
    }
    __syncthreads();

    int p = tid >> 6, t = tid & 63;
    fft256<false>(&buf[p*SLICE], stw, t, true);

    float2* out = g_zf + (size_t)sc*WF*HH + h0;
    for (int i = tid; i < WF*16; i += 512) {
        int k = i >> 4, hh2 = i & 15;
        float2* Z = &buf[(hh2>>1)*SLICE];
        int m = (256 - k) & 255;
        float2 zk = Z[swz(k)], zm = Z[swz(m)];
        float2 v;
        if ((hh2 & 1) == 0)
            v = make_float2(0.5f*(zk.x + zm.x), 0.5f*(zk.y - zm.y));  // A[k]
        else
            v = make_float2(0.5f*(zk.y + zm.y), 0.5f*(zm.x - zk.x));  // B[k]
        out[(size_t)k*HH + hh2] = v;
    }
}

// ---------------- stage B: FFT along H, wf product, channel-sum, iFFT along H ----------------
__global__ void k_colprod(){
    __shared__ float2 buf[4*SLICE];
    __shared__ float2 acc[4*256];
    __shared__ float2 stw[256];
    int tid = threadIdx.x;               // 256
    int k = blockIdx.x;                  // 0..128
    int s = blockIdx.y;
    stw[tid] = g_tw[tid];
    for (int i = tid; i < 1024; i += 256) acc[i] = make_float2(0.f, 0.f);
    __syncthreads();

    int p = tid >> 6, t = tid & 63;
    float2* A = &buf[p*SLICE];

    for (int ic = 0; ic < 8; ic++) {
        int c = p + 4*ic;
        const float2* src = g_zf + ((size_t)(s*CC + c)*WF + k)*HH;
        #pragma unroll
        for (int m = 0; m < 4; m++) A[swz(t + 64*m)] = src[t + 64*m];
        __syncthreads();
        fft256<false>(A, stw, t, true);
        const float2* wp = g_wft + ((size_t)k*CC + c)*HH;
        #pragma unroll
        for (int m = 0; m < 4; m++) {
            int hf = t + 64*m;
            float2 zv = A[swz(hf)];
            float2 wv = wp[hf];
            float2 a = acc[p*256 + hf];
            a.x += wv.x * zv.x;        // g_re = wf_re * zf_re
            a.y -= wv.y * zv.y;        // g_im = -wf_im * zf_im
            acc[p*256 + hf] = a;
        }
        __syncthreads();
    }
    // combine 4 partial accumulators -> slice 0 buffer
    {
        float2 g0 = acc[tid], g1 = acc[256 + tid], g2 = acc[512 + tid], g3 = acc[768 + tid];
        buf[swz(tid)] = make_float2(g0.x + g1.x + g2.x + g3.x,
                                    g0.y + g1.y + g2.y + g3.y);
    }
    __syncthreads();
    fft256<true>(&buf[0], stw, t, tid < 64);
    float2 v = buf[swz(tid)];
    g_ghat[((size_t)s*WF + k)*HH + tid] = make_float2(v.x*(1.f/256.f), v.y*(1.f/256.f));
}

// ---------------- stage C: irfft along W (2 rows packed) -> output ----------------
__global__ void k_irow(float* __restrict__ out){
    __shared__ float2 buf[4*SLICE];
    __shared__ float2 stw[256];
    int tid = threadIdx.x;               // 256
    int s  = blockIdx.y;
    int h0 = blockIdx.x * 8;
    stw[tid] = g_tw[tid];
    __syncthreads();

    int p = tid >> 6, t = tid & 63;
    int ha = h0 + 2*p, hb = ha + 1;
    const float2* G = g_ghat + (size_t)s*WF*HH;
    float2* A = &buf[p*SLICE];

    #pragma unroll
    for (int m = 0; m < 4; m++) {
        int kk = t + 64*m;
        int srck = (kk <= 128) ? kk : (256 - kk);
        float2 a = G[(size_t)srck*HH + ha];
        float2 b = G[(size_t)srck*HH + hb];
        if (srck == 0 || srck == 128) { a.y = 0.f; b.y = 0.f; }   // C2R drops Im of DC/Nyquist
        float2 zv;
        if (kk <= 128) zv = make_float2(a.x - b.y, a.y + b.x);    // a + i b
        else           zv = make_float2(a.x + b.y, b.x - a.y);    // conj(a) + i conj(b)
        A[swz(kk)] = zv;
    }
    __syncthreads();
    fft256<true>(A, stw, t, true);

    float* o = out + (size_t)s*HH*WW;
    #pragma unroll
    for (int m = 0; m < 4; m++) {
        int wj = t + 64*m;
        float2 zv = A[swz(wj)];
        o[(size_t)ha*WW + wj] = zv.x * (1.f/256.f);
        o[(size_t)hb*WW + wj] = zv.y * (1.f/256.f);
    }
}

extern "C" void kernel_launch(void* const* d_in, const int* in_sizes, int n_in,
                              void* d_out, int out_size){
    const float* z    = (const float*)d_in[0];
    const float* cosw = (const float*)d_in[1];
    const float* wf   = (const float*)d_in[2];
    const float* w1   = (const float*)d_in[3];
    const float* b1   = (const float*)d_in[4];
    const float* w2   = (const float*)d_in[5];
    const float* b2   = (const float*)d_in[6];
    float* out = (float*)d_out;

    const int smem2 = (10880 + 9216 + 8192) * 4;   // 113152 B
    cudaFuncSetAttribute(k_conv2, cudaFuncAttributeMaxDynamicSharedMemorySize, smem2);

    k_init<<<1024, 512>>>(wf);

    dim3 gc(8, 32, SS);
    k_conv1<<<gc, 256>>>(z, w1, b1);
    k_conv2<<<gc, 256, smem2>>>(w2, b2, cosw);

    dim3 ga(16, SS*CC);
    k_fftrow<<<ga, 512>>>();

    dim3 gb(WF, SS);
    k_colprod<<<gb, 256>>>();

    dim3 gi(32, SS);
    k_irow<<<gi, 256>>>(out);
}

// round 4
// speedup vs baseline: 1.2106x; 1.2106x over previous
#include <cuda_runtime.h>
#include <cuda_bf16.h>
#include <math.h>
#include <stdint.h>

#define SS   64
#define CC   32
#define CIN  3
#define HH   256
#define WW   256
#define WF   129

// ---------------- device scratch ----------------
__device__ __nv_bfloat16 g_x1h[(size_t)SS*HH*WW*CC];   // conv1 out hi split, [s][h][w][c]
__device__ __nv_bfloat16 g_x1l[(size_t)SS*HH*WW*CC];   // conv1 out lo split
__device__ float  g_x2[(size_t)SS*CC*HH*WW];           // conv2+LRN+coswin, [s][c][h][w]
__device__ float2 g_zf[(size_t)SS*CC*WF*HH];           // row-rfft, [s][c][k][h]
__device__ float2 g_ghat[(size_t)SS*WF*HH];            // after ifft along H, [s][k][h]
__device__ float2 g_wft[(size_t)WF*CC*HH];             // wf transposed [k][c][hf]
__device__ float2 g_tw[256];                           // e^{-2pi i m/256}
__device__ __nv_bfloat16 g_w2b[2*288*32];              // [split][k=tap*32+ci][co] bf16

__device__ __forceinline__ int swz(int i){ return i + (i>>4); }
#define SLICE 272

__device__ __forceinline__ float2 cmul(float2 a, float2 b){
    return make_float2(a.x*b.x - a.y*b.y, a.x*b.y + a.y*b.x);
}

__device__ __forceinline__ uint32_t smem_u32(const void* p) {
    uint32_t a;
    asm("{ .reg .u64 t; cvta.to.shared.u64 t, %1; cvt.u32.u64 %0, t; }" : "=r"(a) : "l"(p));
    return a;
}

__device__ __forceinline__ void ldsm_x4(uint32_t* r, uint32_t addr){
    asm volatile("ldmatrix.sync.aligned.m8n8.x4.shared.b16 {%0,%1,%2,%3}, [%4];"
        : "=r"(r[0]),"=r"(r[1]),"=r"(r[2]),"=r"(r[3]) : "r"(addr));
}
__device__ __forceinline__ void ldsm_x4t(uint32_t* r, uint32_t addr){
    asm volatile("ldmatrix.sync.aligned.m8n8.x4.trans.shared.b16 {%0,%1,%2,%3}, [%4];"
        : "=r"(r[0]),"=r"(r[1]),"=r"(r[2]),"=r"(r[3]) : "r"(addr));
}
__device__ __forceinline__ void mma16816(float* d, const uint32_t* a, const uint32_t* b){
    asm volatile("mma.sync.aligned.m16n8k16.row.col.f32.bf16.bf16.f32 "
        "{%0,%1,%2,%3}, {%4,%5,%6,%7}, {%8,%9}, {%0,%1,%2,%3};"
        : "+f"(d[0]), "+f"(d[1]), "+f"(d[2]), "+f"(d[3])
        : "r"(a[0]), "r"(a[1]), "r"(a[2]), "r"(a[3]), "r"(b[0]), "r"(b[1]));
}

// Radix-4 Stockham FFT-256 on shared memory (64 working threads per slice).
template<bool INV>
__device__ void fft256(float2* A, const float2* tw, int t, bool active){
    #pragma unroll
    for (int L = 1; L <= 64; L *= 4) {
        float2 X0, X1, X2, X3;
        int base = 0;
        if (active) {
            int k = t & (L-1);
            float2 x0 = A[swz(t)];
            float2 x1 = A[swz(t+64)];
            float2 x2 = A[swz(t+128)];
            float2 x3 = A[swz(t+192)];
            int tm = k * (64 / L);
            float2 w1 = tw[tm];
            float2 w2 = tw[(2*tm) & 255];
            float2 w3 = tw[(3*tm) & 255];
            if (INV){ w1.y = -w1.y; w2.y = -w2.y; w3.y = -w3.y; }
            x1 = cmul(x1, w1); x2 = cmul(x2, w2); x3 = cmul(x3, w3);
            float2 y0 = make_float2(x0.x+x2.x, x0.y+x2.y);
            float2 y1 = make_float2(x0.x-x2.x, x0.y-x2.y);
            float2 y2 = make_float2(x1.x+x3.x, x1.y+x3.y);
            float2 d  = make_float2(x1.x-x3.x, x1.y-x3.y);
            float2 y3 = INV ? make_float2(-d.y,  d.x)
                            : make_float2( d.y, -d.x);
            X0 = make_float2(y0.x+y2.x, y0.y+y2.y);
            X1 = make_float2(y1.x+y3.x, y1.y+y3.y);
            X2 = make_float2(y0.x-y2.x, y0.y-y2.y);
            X3 = make_float2(y1.x-y3.x, y1.y-y3.y);
            base = (t - k)*4 + k;
        }
        __syncthreads();
        if (active) {
            A[swz(base      )] = X0;
            A[swz(base +   L)] = X1;
            A[swz(base + 2*L)] = X2;
            A[swz(base + 3*L)] = X3;
        }
        __syncthreads();
    }
}

// ---------------- init: twiddles + wf transpose + split weights ----------------
__global__ void k_init(const float* __restrict__ wf, const float* __restrict__ w2){
    int tid = blockIdx.x * blockDim.x + threadIdx.x;
    int stride = gridDim.x * blockDim.x;
    if (tid < 256) {
        double ang = -6.283185307179586476925286766559 * (double)tid / 256.0;
        g_tw[tid] = make_float2((float)cos(ang), (float)sin(ang));
    }
    for (int i = tid; i < 2*288*32; i += stride) {
        int sp = i / 9216;
        int r  = i % 9216;
        int k  = r >> 5, co = r & 31;
        int tap = k >> 5, ci = k & 31;
        int kh = tap / 3, kw = tap % 3;
        float f = w2[((co*32 + ci)*3 + kh)*3 + kw];
        __nv_bfloat16 hi = __float2bfloat16(f);
        g_w2b[i] = (sp == 0) ? hi : __float2bfloat16(f - __bfloat162float(hi));
    }
    int total = WF*CC*HH;
    for (int i = tid; i < total; i += stride) {
        int hf = i & 255;
        int c  = (i >> 8) & 31;
        int k  = i >> 13;
        const float* p = wf + (((size_t)c*HH + hf)*WF + k)*2;
        g_wft[i] = make_float2(p[0], p[1]);
    }
}

// ---------------- conv1 + relu -> split bf16, [s][h][w][c] ----------------
__global__ void k_conv1(const float* __restrict__ z, const float* __restrict__ w1,
                        const float* __restrict__ b1){
    __shared__ float sIn[3*10*34];
    __shared__ float sW[27*32];
    int s  = blockIdx.z;
    int w0 = blockIdx.x * 32, h0 = blockIdx.y * 8;
    int tid = threadIdx.x;

    for (int i = tid; i < 27*32; i += 256)
        sW[i] = w1[(size_t)(i & 31)*27 + (i >> 5)];
    for (int i = tid; i < 3*10*34; i += 256) {
        int ci = i / 340, rem = i % 340, rr = rem / 34, cc = rem % 34;
        int gh = h0 + rr - 1, gw = w0 + cc - 1;
        float v = 0.f;
        if (gh >= 0 && gh < HH && gw >= 0 && gw < WW)
            v = z[(((size_t)s*CIN + ci)*HH + gh)*WW + gw];
        sIn[i] = v;
    }
    __syncthreads();

    int wg = tid & 7, r = (tid >> 3) & 7, cob = tid >> 6;
    int co0 = cob * 8;
    float acc[4][8];
    #pragma unroll
    for (int i = 0; i < 4; i++)
        #pragma unroll
        for (int j = 0; j < 8; j++) acc[i][j] = b1[co0 + j];

    #pragma unroll
    for (int ci = 0; ci < 3; ci++)
      #pragma unroll
      for (int kh = 0; kh < 3; kh++) {
        const float* rowp = &sIn[(ci*10 + r + kh)*34];
        #pragma unroll
        for (int kw = 0; kw < 3; kw++) {
            float x0 = rowp[wg      + kw];
            float x1 = rowp[wg + 8  + kw];
            float x2 = rowp[wg + 16 + kw];
            float x3 = rowp[wg + 24 + kw];
            const float* wp = &sW[((ci*3 + kh)*3 + kw)*32 + co0];
            #pragma unroll
            for (int j = 0; j < 8; j++) {
                float wv = wp[j];
                acc[0][j] += x0*wv; acc[1][j] += x1*wv;
                acc[2][j] += x2*wv; acc[3][j] += x3*wv;
            }
        }
      }

    int hh = h0 + r;
    #pragma unroll
    for (int i = 0; i < 4; i++) {
        int ww = w0 + wg + 8*i;
        size_t base = (((size_t)s*HH + hh)*WW + ww)*CC + co0;
        #pragma unroll
        for (int j = 0; j < 8; j++) {
            float v = acc[i][j];
            v = v > 0.f ? v : 0.f;
            __nv_bfloat16 hi = __float2bfloat16(v);
            g_x1h[base + j] = hi;
            g_x1l[base + j] = __float2bfloat16(v - __bfloat162float(hi));
        }
    }
}

// ---------------- conv2 via mma.sync bf16 (3-product split) + LRN + cos window ----------------
// dynamic smem layout (bytes):
//  [0, 36864)       B image, 2 splits x 288 k-rows x 64B (XOR-swizzled 16B units)
//  [36864, 49920)   raw halo tile hi: 204 rows (6h x 34w) x 64B (swizzled)
//  [49920, 62976)   raw halo tile lo
//  [62976, 79360)   sOut: 32 co x 128 px floats
//  [79360, 79488)   bias
#define RAWH_OFF 36864u
#define RAWL_OFF 49920u
#define OUT_OFF  62976u
#define BIAS_OFF 79360u
#define SMEM2_BYTES 79488

__global__ void __launch_bounds__(128, 2)
k_conv2mma(const float* __restrict__ b2, const float* __restrict__ coswin){
    extern __shared__ __align__(16) uint8_t smem[];
    uint32_t sb = smem_u32(smem);
    float* sOut  = (float*)(smem + OUT_OFF);
    float* sBias = (float*)(smem + BIAS_OFF);

    const int tid = threadIdx.x;
    const int wid = tid >> 5, lane = tid & 31;
    const int s  = blockIdx.z;
    const int h0 = blockIdx.y * 4, w0 = blockIdx.x * 32;

    if (tid < 32) sBias[tid] = b2[tid];

    // B image copy with swizzle
    const uint4* wsrc = (const uint4*)g_w2b;
    for (int u = tid; u < 2304; u += 128) {
        int sp = (u >= 1152) ? 1 : 0;
        int r  = u - sp*1152;
        int k  = r >> 2, nc = r & 3;
        uint32_t p = (uint32_t)(k*4 + (nc ^ ((k>>1)&3)));
        *(uint4*)(smem + sp*18432 + p*16) = wsrc[u];
    }

    // raw halo tiles (6h x 34w x 32ci), OOB -> 0, swizzled store
    for (int u = tid; u < 816; u += 128) {
        int rawrow = u >> 2, c = u & 3;
        int hr = rawrow / 34, wc = rawrow % 34;
        int gh = h0 - 1 + hr, gw = w0 - 1 + wc;
        uint4 vh = make_uint4(0,0,0,0), vl = make_uint4(0,0,0,0);
        if (gh >= 0 && gh < HH && gw >= 0 && gw < WW) {
            size_t gi = ((size_t)((s*HH + gh))*WW + gw)*4 + c;
            vh = ((const uint4*)g_x1h)[gi];
            vl = ((const uint4*)g_x1l)[gi];
        }
        uint32_t p = (uint32_t)(rawrow*4 + (c ^ ((rawrow>>1)&3)));
        *(uint4*)(smem + RAWH_OFF + p*16) = vh;
        *(uint4*)(smem + RAWL_OFF + p*16) = vl;
    }
    __syncthreads();

    const int t15 = lane & 15;
    const int tHi = lane >> 4;           // 0/1: second 16B chunk / second n-block
    const int hl  = wid;
    const int swb = (t15 >> 1) & 3;

    // B fragment base addresses (k-term added per step as st*1024)
    uint32_t bA[2][2];
    #pragma unroll
    for (int sp = 0; sp < 2; sp++)
        #pragma unroll
        for (int nbx = 0; nbx < 2; nbx++)
            bA[sp][nbx] = sb + (uint32_t)sp*18432u
                        + (uint32_t)((t15*4 + ((nbx*2 + tHi) ^ swb))*16);

    float d[2][4][4];
    #pragma unroll
    for (int mb = 0; mb < 2; mb++)
        #pragma unroll
        for (int j = 0; j < 4; j++)
            #pragma unroll
            for (int e = 0; e < 4; e++) d[mb][j][e] = 0.f;

    #pragma unroll
    for (int st = 0; st < 18; st++) {
        const int tap = st >> 1, kh = tap/3, kw = tap - kh*3;
        const int c0  = (st & 1) * 2;

        uint32_t ah[2][4], al[2][4];
        #pragma unroll
        for (int mb = 0; mb < 2; mb++) {
            int rawrow = (hl + kh)*34 + kw + mb*16 + t15;
            int cc = c0 + tHi;
            uint32_t p = (uint32_t)(rawrow*4 + (cc ^ ((rawrow>>1)&3)));
            ldsm_x4(ah[mb], sb + RAWH_OFF + p*16);
            ldsm_x4(al[mb], sb + RAWL_OFF + p*16);
        }
        uint32_t wh[8], wl[8];
        ldsm_x4t(wh,     bA[0][0] + (uint32_t)st*1024u);
        ldsm_x4t(wh + 4, bA[0][1] + (uint32_t)st*1024u);
        ldsm_x4t(wl,     bA[1][0] + (uint32_t)st*1024u);
        ldsm_x4t(wl + 4, bA[1][1] + (uint32_t)st*1024u);

        #pragma unroll
        for (int mb = 0; mb < 2; mb++)
            #pragma unroll
            for (int j = 0; j < 4; j++) {
                mma16816(d[mb][j], ah[mb], wh + 2*j);
                mma16816(d[mb][j], ah[mb], wl + 2*j);
                mma16816(d[mb][j], al[mb], wh + 2*j);
            }
    }

    // epilogue: regs -> sOut [co][px]
    #pragma unroll
    for (int mb = 0; mb < 2; mb++) {
        int px = hl*32 + mb*16 + (lane >> 2);
        #pragma unroll
        for (int j = 0; j < 4; j++) {
            int co = j*8 + (lane & 3)*2;
            sOut[co*128 + px]         = d[mb][j][0] + sBias[co];
            sOut[(co+1)*128 + px]     = d[mb][j][1] + sBias[co+1];
            sOut[co*128 + px + 8]     = d[mb][j][2] + sBias[co];
            sOut[(co+1)*128 + px + 8] = d[mb][j][3] + sBias[co+1];
        }
    }
    __syncwarp();

    // LRN + cos window; thread t handles px=t (same warp that produced it)
    {
        int px = tid;
        int hh = h0 + (px >> 5), ww = w0 + (px & 31);
        float yv[32];
        #pragma unroll
        for (int c = 0; c < 32; c++) yv[c] = sOut[c*128 + px];
        float cw = coswin[(size_t)hh*WW + ww];
        float win = yv[0]*yv[0] + yv[1]*yv[1] + yv[2]*yv[2];
        size_t obase = ((size_t)s*CC*HH + (size_t)hh)*WW + ww;
        #pragma unroll
        for (int c = 0; c < 32; c++) {
            float t = 1.0f + 2e-5f * win;
            float v = yv[c] * __powf(t, -0.75f) * cw;
            g_x2[obase + (size_t)c*HH*WW] = v;
            if (c + 3 < 32) win += yv[c+3]*yv[c+3];
            if (c - 2 >= 0) win -= yv[c-2]*yv[c-2];
        }
    }
}

// ---------------- stage A: row rfft (2 rows packed), transposed store ----------------
__global__ void k_fftrow(){
    __shared__ float2 buf[8*SLICE];
    __shared__ float2 stw[256];
    int tid = threadIdx.x;               // 512
    int sc  = blockIdx.y;                // s*32 + c
    int h0  = blockIdx.x * 16;
    if (tid < 256) stw[tid] = g_tw[tid];

    const float* src = g_x2 + (size_t)sc*HH*WW + (size_t)h0*WW;
    for (int i = tid; i < 16*256; i += 512) {
        int row = i >> 8, j = i & 255;
        float v = src[(size_t)row*WW + j];
        float* dst = (float*)&buf[(row>>1)*SLICE + swz(j)];
        dst[row & 1] = v;
    }
    __syncthreads();

    int p = tid >> 6, t = tid & 63;
    fft256<false>(&buf[p*SLICE], stw, t, true);

    float2* out = g_zf + (size_t)sc*WF*HH + h0;
    for (int i = tid; i < WF*16; i += 512) {
        int k = i >> 4, hh2 = i & 15;
        float2* Z = &buf[(hh2>>1)*SLICE];
        int m = (256 - k) & 255;
        float2 zk = Z[swz(k)], zm = Z[swz(m)];
        float2 v;
        if ((hh2 & 1) == 0)
            v = make_float2(0.5f*(zk.x + zm.x), 0.5f*(zk.y - zm.y));  // A[k]
        else
            v = make_float2(0.5f*(zk.y + zm.y), 0.5f*(zm.x - zk.x));  // B[k]
        out[(size_t)k*HH + hh2] = v;
    }
}

// ---------------- stage B: FFT along H, wf product, channel-sum, iFFT along H ----------------
__global__ void k_colprod(){
    __shared__ float2 buf[4*SLICE];
    __shared__ float2 acc[4*256];
    __shared__ float2 stw[256];
    int tid = threadIdx.x;               // 256
    int k = blockIdx.x;                  // 0..128
    int s = blockIdx.y;
    stw[tid] = g_tw[tid];
    for (int i = tid; i < 1024; i += 256) acc[i] = make_float2(0.f, 0.f);
    __syncthreads();

    int p = tid >> 6, t = tid & 63;
    float2* A = &buf[p*SLICE];

    for (int ic = 0; ic < 8; ic++) {
        int c = p + 4*ic;
        const float2* src = g_zf + ((size_t)(s*CC + c)*WF + k)*HH;
        #pragma unroll
        for (int m = 0; m < 4; m++) A[swz(t + 64*m)] = src[t + 64*m];
        __syncthreads();
        fft256<false>(A, stw, t, true);
        const float2* wp = g_wft + ((size_t)k*CC + c)*HH;
        #pragma unroll
        for (int m = 0; m < 4; m++) {
            int hf = t + 64*m;
            float2 zv = A[swz(hf)];
            float2 wv = wp[hf];
            float2 a = acc[p*256 + hf];
            a.x += wv.x * zv.x;        // g_re = wf_re * zf_re
            a.y -= wv.y * zv.y;        // g_im = -wf_im * zf_im
            acc[p*256 + hf] = a;
        }
        __syncthreads();
    }
    {
        float2 g0 = acc[tid], g1 = acc[256 + tid], g2 = acc[512 + tid], g3 = acc[768 + tid];
        buf[swz(tid)] = make_float2(g0.x + g1.x + g2.x + g3.x,
                                    g0.y + g1.y + g2.y + g3.y);
    }
    __syncthreads();
    fft256<true>(&buf[0], stw, t, tid < 64);
    float2 v = buf[swz(tid)];
    g_ghat[((size_t)s*WF + k)*HH + tid] = make_float2(v.x*(1.f/256.f), v.y*(1.f/256.f));
}

// ---------------- stage C: irfft along W (2 rows packed) -> output ----------------
__global__ void k_irow(float* __restrict__ out){
    __shared__ float2 buf[4*SLICE];
    __shared__ float2 stw[256];
    int tid = threadIdx.x;               // 256
    int s  = blockIdx.y;
    int h0 = blockIdx.x * 8;
    stw[tid] = g_tw[tid];
    __syncthreads();

    int p = tid >> 6, t = tid & 63;
    int ha = h0 + 2*p, hb = ha + 1;
    const float2* G = g_ghat + (size_t)s*WF*HH;
    float2* A = &buf[p*SLICE];

    #pragma unroll
    for (int m = 0; m < 4; m++) {
        int kk = t + 64*m;
        int srck = (kk <= 128) ? kk : (256 - kk);
        float2 a = G[(size_t)srck*HH + ha];
        float2 b = G[(size_t)srck*HH + hb];
        if (srck == 0 || srck == 128) { a.y = 0.f; b.y = 0.f; }   // C2R drops Im of DC/Nyquist
        float2 zv;
        if (kk <= 128) zv = make_float2(a.x - b.y, a.y + b.x);    // a + i b
        else           zv = make_float2(a.x + b.y, b.x - a.y);    // conj(a) + i conj(b)
        A[swz(kk)] = zv;
    }
    __syncthreads();
    fft256<true>(A, stw, t, true);

    float* o = out + (size_t)s*HH*WW;
    #pragma unroll
    for (int m = 0; m < 4; m++) {
        int wj = t + 64*m;
        float2 zv = A[swz(wj)];
        o[(size_t)ha*WW + wj] = zv.x * (1.f/256.f);
        o[(size_t)hb*WW + wj] = zv.y * (1.f/256.f);
    }
}

extern "C" void kernel_launch(void* const* d_in, const int* in_sizes, int n_in,
                              void* d_out, int out_size){
    const float* z    = (const float*)d_in[0];
    const float* cosw = (const float*)d_in[1];
    const float* wf   = (const float*)d_in[2];
    const float* w1   = (const float*)d_in[3];
    const float* b1   = (const float*)d_in[4];
    const float* w2   = (const float*)d_in[5];
    const float* b2   = (const float*)d_in[6];
    float* out = (float*)d_out;

    cudaFuncSetAttribute(k_conv2mma, cudaFuncAttributeMaxDynamicSharedMemorySize, SMEM2_BYTES);

    k_init<<<1024, 512>>>(wf, w2);

    dim3 gc(8, 32, SS);
    k_conv1<<<gc, 256>>>(z, w1, b1);

    dim3 gm(8, 64, SS);
    k_conv2mma<<<gm, 128, SMEM2_BYTES>>>(b2, cosw);

    dim3 ga(16, SS*CC);
    k_fftrow<<<ga, 512>>>();

    dim3 gb(WF, SS);
    k_colprod<<<gb, 256>>>();

    dim3 gi(32, SS);
    k_irow<<<gi, 256>>>(out);
}

// round 5
// speedup vs baseline: 1.2870x; 1.0631x over previous
#include <cuda_runtime.h>
#include <cuda_bf16.h>
#include <math.h>
#include <stdint.h>

#define SS   64
#define CC   32
#define CIN  3
#define HH   256
#define WW   256
#define WF   129

// ---------------- device scratch ----------------
__device__ __nv_bfloat16 g_x1h[(size_t)SS*HH*WW*CC];   // conv1 out hi split, [s][h][w][c]
__device__ __nv_bfloat16 g_x1l[(size_t)SS*HH*WW*CC];   // conv1 out lo split
__device__ float  g_x2[(size_t)SS*CC*HH*WW];           // conv2+LRN+coswin, [s][c][h][w]
__device__ float2 g_zf[(size_t)SS*CC*WF*HH];           // row-rfft, [s][c][k][h]
__device__ float2 g_ghat[(size_t)SS*WF*HH];            // after ifft along H, [s][k][h]
__device__ float2 g_wft[(size_t)WF*CC*HH];             // wf transposed [k][c][hf]
__device__ float2 g_tw[256];                           // e^{-2pi i m/256}
__device__ __nv_bfloat16 g_w2b[2*288*32];              // [split][k=tap*32+ci][co] bf16

__device__ __forceinline__ int swz(int i){ return i + (i>>4); }
#define SLICE 272

__device__ __forceinline__ float2 cmul(float2 a, float2 b){
    return make_float2(a.x*b.x - a.y*b.y, a.x*b.y + a.y*b.x);
}

__device__ __forceinline__ uint32_t smem_u32(const void* p) {
    uint32_t a;
    asm("{ .reg .u64 t; cvta.to.shared.u64 t, %1; cvt.u32.u64 %0, t; }" : "=r"(a) : "l"(p));
    return a;
}

__device__ __forceinline__ void ldsm_x4(uint32_t* r, uint32_t addr){
    asm volatile("ldmatrix.sync.aligned.m8n8.x4.shared.b16 {%0,%1,%2,%3}, [%4];"
        : "=r"(r[0]),"=r"(r[1]),"=r"(r[2]),"=r"(r[3]) : "r"(addr));
}
__device__ __forceinline__ void ldsm_x4t(uint32_t* r, uint32_t addr){
    asm volatile("ldmatrix.sync.aligned.m8n8.x4.trans.shared.b16 {%0,%1,%2,%3}, [%4];"
        : "=r"(r[0]),"=r"(r[1]),"=r"(r[2]),"=r"(r[3]) : "r"(addr));
}
__device__ __forceinline__ void mma16816(float* d, const uint32_t* a, const uint32_t* b){
    asm volatile("mma.sync.aligned.m16n8k16.row.col.f32.bf16.bf16.f32 "
        "{%0,%1,%2,%3}, {%4,%5,%6,%7}, {%8,%9}, {%0,%1,%2,%3};"
        : "+f"(d[0]), "+f"(d[1]), "+f"(d[2]), "+f"(d[3])
        : "r"(a[0]), "r"(a[1]), "r"(a[2]), "r"(a[3]), "r"(b[0]), "r"(b[1]));
}

// Radix-4 Stockham FFT-256 on shared memory (64 working threads per slice).
template<bool INV>
__device__ void fft256(float2* A, const float2* tw, int t, bool active){
    #pragma unroll
    for (int L = 1; L <= 64; L *= 4) {
        float2 X0, X1, X2, X3;
        int base = 0;
        if (active) {
            int k = t & (L-1);
            float2 x0 = A[swz(t)];
            float2 x1 = A[swz(t+64)];
            float2 x2 = A[swz(t+128)];
            float2 x3 = A[swz(t+192)];
            int tm = k * (64 / L);
            float2 w1 = tw[tm];
            float2 w2 = tw[(2*tm) & 255];
            float2 w3 = tw[(3*tm) & 255];
            if (INV){ w1.y = -w1.y; w2.y = -w2.y; w3.y = -w3.y; }
            x1 = cmul(x1, w1); x2 = cmul(x2, w2); x3 = cmul(x3, w3);
            float2 y0 = make_float2(x0.x+x2.x, x0.y+x2.y);
            float2 y1 = make_float2(x0.x-x2.x, x0.y-x2.y);
            float2 y2 = make_float2(x1.x+x3.x, x1.y+x3.y);
            float2 d  = make_float2(x1.x-x3.x, x1.y-x3.y);
            float2 y3 = INV ? make_float2(-d.y,  d.x)
                            : make_float2( d.y, -d.x);
            X0 = make_float2(y0.x+y2.x, y0.y+y2.y);
            X1 = make_float2(y1.x+y3.x, y1.y+y3.y);
            X2 = make_float2(y0.x-y2.x, y0.y-y2.y);
            X3 = make_float2(y1.x-y3.x, y1.y-y3.y);
            base = (t - k)*4 + k;
        }
        __syncthreads();
        if (active) {
            A[swz(base      )] = X0;
            A[swz(base +   L)] = X1;
            A[swz(base + 2*L)] = X2;
            A[swz(base + 3*L)] = X3;
        }
        __syncthreads();
    }
}

// ---------------- init: twiddles + wf transpose + split weights ----------------
__global__ void k_init(const float* __restrict__ wf, const float* __restrict__ w2){
    int tid = blockIdx.x * blockDim.x + threadIdx.x;
    int stride = gridDim.x * blockDim.x;
    if (tid < 256) {
        double ang = -6.283185307179586476925286766559 * (double)tid / 256.0;
        g_tw[tid] = make_float2((float)cos(ang), (float)sin(ang));
    }
    for (int i = tid; i < 2*288*32; i += stride) {
        int sp = i / 9216;
        int r  = i % 9216;
        int k  = r >> 5, co = r & 31;
        int tap = k >> 5, ci = k & 31;
        int kh = tap / 3, kw = tap % 3;
        float f = w2[((co*32 + ci)*3 + kh)*3 + kw];
        __nv_bfloat16 hi = __float2bfloat16(f);
        g_w2b[i] = (sp == 0) ? hi : __float2bfloat16(f - __bfloat162float(hi));
    }
    int total = WF*CC*HH;
    for (int i = tid; i < total; i += stride) {
        int hf = i & 255;
        int c  = (i >> 8) & 31;
        int k  = i >> 13;
        const float* p = wf + (((size_t)c*HH + hf)*WF + k)*2;
        g_wft[i] = make_float2(p[0], p[1]);
    }
}

// ---------------- conv1 + relu -> split bf16, [s][h][w][c] ----------------
__global__ void k_conv1(const float* __restrict__ z, const float* __restrict__ w1,
                        const float* __restrict__ b1){
    __shared__ float sIn[3*10*34];
    __shared__ float sW[27*32];
    int s  = blockIdx.z;
    int w0 = blockIdx.x * 32, h0 = blockIdx.y * 8;
    int tid = threadIdx.x;

    for (int i = tid; i < 27*32; i += 256)
        sW[i] = w1[(size_t)(i & 31)*27 + (i >> 5)];
    for (int i = tid; i < 3*10*34; i += 256) {
        int ci = i / 340, rem = i % 340, rr = rem / 34, cc = rem % 34;
        int gh = h0 + rr - 1, gw = w0 + cc - 1;
        float v = 0.f;
        if (gh >= 0 && gh < HH && gw >= 0 && gw < WW)
            v = z[(((size_t)s*CIN + ci)*HH + gh)*WW + gw];
        sIn[i] = v;
    }
    __syncthreads();

    int wg = tid & 7, r = (tid >> 3) & 7, cob = tid >> 6;
    int co0 = cob * 8;
    float acc[4][8];
    #pragma unroll
    for (int i = 0; i < 4; i++)
        #pragma unroll
        for (int j = 0; j < 8; j++) acc[i][j] = b1[co0 + j];

    #pragma unroll
    for (int ci = 0; ci < 3; ci++)
      #pragma unroll
      for (int kh = 0; kh < 3; kh++) {
        const float* rowp = &sIn[(ci*10 + r + kh)*34];
        #pragma unroll
        for (int kw = 0; kw < 3; kw++) {
            float x0 = rowp[wg      + kw];
            float x1 = rowp[wg + 8  + kw];
            float x2 = rowp[wg + 16 + kw];
            float x3 = rowp[wg + 24 + kw];
            const float* wp = &sW[((ci*3 + kh)*3 + kw)*32 + co0];
            #pragma unroll
            for (int j = 0; j < 8; j++) {
                float wv = wp[j];
                acc[0][j] += x0*wv; acc[1][j] += x1*wv;
                acc[2][j] += x2*wv; acc[3][j] += x3*wv;
            }
        }
      }

    int hh = h0 + r;
    #pragma unroll
    for (int i = 0; i < 4; i++) {
        int ww = w0 + wg + 8*i;
        size_t base = (((size_t)s*HH + hh)*WW + ww)*CC + co0;
        #pragma unroll
        for (int j = 0; j < 8; j++) {
            float v = acc[i][j];
            v = v > 0.f ? v : 0.f;
            __nv_bfloat16 hi = __float2bfloat16(v);
            g_x1h[base + j] = hi;
            g_x1l[base + j] = __float2bfloat16(v - __bfloat162float(hi));
        }
    }
}

// ---------------- conv2 via mma.sync bf16 (3-product split, K split over 2 warpgroups) ----------------
// dynamic smem layout (bytes):
//  [0, 36864)       B image, 2 splits x 288 k-rows x 64B (XOR-swizzled 16B units)
//  [36864, 49920)   raw halo tile hi: 204 rows (6h x 34w) x 64B (swizzled)
//  [49920, 62976)   raw halo tile lo
//  [62976, 79360)   sOut: 32 co x 128 px floats
//  [79360, 79488)   bias
#define RAWH_OFF 36864u
#define RAWL_OFF 49920u
#define OUT_OFF  62976u
#define BIAS_OFF 79360u
#define SMEM2_BYTES 79488

__global__ void __launch_bounds__(256, 2)
k_conv2mma(const float* __restrict__ b2, const float* __restrict__ coswin){
    extern __shared__ __align__(16) uint8_t smem[];
    uint32_t sb = smem_u32(smem);
    float* sOut  = (float*)(smem + OUT_OFF);
    float* sBias = (float*)(smem + BIAS_OFF);

    const int tid = threadIdx.x;
    const int wid = tid >> 5, lane = tid & 31;
    const int grp = wid >> 2;            // 0: steps 0-8, 1: steps 9-17
    const int hl  = wid & 3;             // h row within tile
    const int s  = blockIdx.z;
    const int h0 = blockIdx.y * 4, w0 = blockIdx.x * 32;

    if (tid < 32) sBias[tid] = b2[tid];

    // B image copy with swizzle
    const uint4* wsrc = (const uint4*)g_w2b;
    for (int u = tid; u < 2304; u += 256) {
        int sp = (u >= 1152) ? 1 : 0;
        int r  = u - sp*1152;
        int k  = r >> 2, nc = r & 3;
        uint32_t p = (uint32_t)(k*4 + (nc ^ ((k>>1)&3)));
        *(uint4*)(smem + sp*18432 + p*16) = wsrc[u];
    }

    // raw halo tiles (6h x 34w x 32ci), OOB -> 0, swizzled store
    for (int u = tid; u < 816; u += 256) {
        int rawrow = u >> 2, c = u & 3;
        int hr = rawrow / 34, wc = rawrow % 34;
        int gh = h0 - 1 + hr, gw = w0 - 1 + wc;
        uint4 vh = make_uint4(0,0,0,0), vl = make_uint4(0,0,0,0);
        if (gh >= 0 && gh < HH && gw >= 0 && gw < WW) {
            size_t gi = ((size_t)((s*HH + gh))*WW + gw)*4 + c;
            vh = ((const uint4*)g_x1h)[gi];
            vl = ((const uint4*)g_x1l)[gi];
        }
        uint32_t p = (uint32_t)(rawrow*4 + (c ^ ((rawrow>>1)&3)));
        *(uint4*)(smem + RAWH_OFF + p*16) = vh;
        *(uint4*)(smem + RAWL_OFF + p*16) = vl;
    }
    __syncthreads();

    const int t15 = lane & 15;
    const int tHi = lane >> 4;           // 0/1: second 16B chunk / second n-block
    const int swb = (t15 >> 1) & 3;

    // B fragment base addresses (k-term added per step as st*1024)
    uint32_t bA[2][2];
    #pragma unroll
    for (int sp = 0; sp < 2; sp++)
        #pragma unroll
        for (int nbx = 0; nbx < 2; nbx++)
            bA[sp][nbx] = sb + (uint32_t)sp*18432u
                        + (uint32_t)((t15*4 + ((nbx*2 + tHi) ^ swb))*16);

    float d[2][4][4];
    #pragma unroll
    for (int mb = 0; mb < 2; mb++)
        #pragma unroll
        for (int j = 0; j < 4; j++)
            #pragma unroll
            for (int e = 0; e < 4; e++) d[mb][j][e] = 0.f;

    #pragma unroll
    for (int i = 0; i < 9; i++) {
        const int st  = grp*9 + i;
        const int tap = st >> 1, kh = tap/3, kw = tap - kh*3;
        const int c0  = (st & 1) * 2;

        uint32_t ah[2][4], al[2][4];
        #pragma unroll
        for (int mb = 0; mb < 2; mb++) {
            int rawrow = (hl + kh)*34 + kw + mb*16 + t15;
            int cc = c0 + tHi;
            uint32_t p = (uint32_t)(rawrow*4 + (cc ^ ((rawrow>>1)&3)));
            ldsm_x4(ah[mb], sb + RAWH_OFF + p*16);
            ldsm_x4(al[mb], sb + RAWL_OFF + p*16);
        }
        uint32_t wh[8], wl[8];
        ldsm_x4t(wh,     bA[0][0] + (uint32_t)st*1024u);
        ldsm_x4t(wh + 4, bA[0][1] + (uint32_t)st*1024u);
        ldsm_x4t(wl,     bA[1][0] + (uint32_t)st*1024u);
        ldsm_x4t(wl + 4, bA[1][1] + (uint32_t)st*1024u);

        #pragma unroll
        for (int mb = 0; mb < 2; mb++)
            #pragma unroll
            for (int j = 0; j < 4; j++) {
                mma16816(d[mb][j], ah[mb], wh + 2*j);
                mma16816(d[mb][j], ah[mb], wl + 2*j);
                mma16816(d[mb][j], al[mb], wh + 2*j);
            }
    }

    // epilogue: group 0 writes (+bias), group 1 accumulates
    if (grp == 0) {
        #pragma unroll
        for (int mb = 0; mb < 2; mb++) {
            int px = hl*32 + mb*16 + (lane >> 2);
            #pragma unroll
            for (int j = 0; j < 4; j++) {
                int co = j*8 + (lane & 3)*2;
                sOut[co*128 + px]         = d[mb][j][0] + sBias[co];
                sOut[(co+1)*128 + px]     = d[mb][j][1] + sBias[co+1];
                sOut[co*128 + px + 8]     = d[mb][j][2] + sBias[co];
                sOut[(co+1)*128 + px + 8] = d[mb][j][3] + sBias[co+1];
            }
        }
    }
    __syncthreads();
    if (grp == 1) {
        #pragma unroll
        for (int mb = 0; mb < 2; mb++) {
            int px = hl*32 + mb*16 + (lane >> 2);
            #pragma unroll
            for (int j = 0; j < 4; j++) {
                int co = j*8 + (lane & 3)*2;
                sOut[co*128 + px]         += d[mb][j][0];
                sOut[(co+1)*128 + px]     += d[mb][j][1];
                sOut[co*128 + px + 8]     += d[mb][j][2];
                sOut[(co+1)*128 + px + 8] += d[mb][j][3];
            }
        }
    }
    __syncthreads();

    // LRN + cos window; threads 0-127 handle one pixel each
    if (tid < 128) {
        int px = tid;
        int hh = h0 + (px >> 5), ww = w0 + (px & 31);
        float yv[32];
        #pragma unroll
        for (int c = 0; c < 32; c++) yv[c] = sOut[c*128 + px];
        float cw = coswin[(size_t)hh*WW + ww];
        float win = yv[0]*yv[0] + yv[1]*yv[1] + yv[2]*yv[2];
        size_t obase = ((size_t)s*CC*HH + (size_t)hh)*WW + ww;
        #pragma unroll
        for (int c = 0; c < 32; c++) {
            float t = 1.0f + 2e-5f * win;
            float v = yv[c] * __powf(t, -0.75f) * cw;
            g_x2[obase + (size_t)c*HH*WW] = v;
            if (c + 3 < 32) win += yv[c+3]*yv[c+3];
            if (c - 2 >= 0) win -= yv[c-2]*yv[c-2];
        }
    }
}

// ---------------- stage A: row rfft (2 rows packed), transposed store ----------------
__global__ void k_fftrow(){
    __shared__ float2 buf[8*SLICE];
    __shared__ float2 stw[256];
    int tid = threadIdx.x;               // 512
    int sc  = blockIdx.y;                // s*32 + c
    int h0  = blockIdx.x * 16;
    if (tid < 256) stw[tid] = g_tw[tid];

    const float* src = g_x2 + (size_t)sc*HH*WW + (size_t)h0*WW;
    for (int i = tid; i < 16*256; i += 512) {
        int row = i >> 8, j = i & 255;
        float v = src[(size_t)row*WW + j];
        float* dst = (float*)&buf[(row>>1)*SLICE + swz(j)];
        dst[row & 1] = v;
    }
    __syncthreads();

    int p = tid >> 6, t = tid & 63;
    fft256<false>(&buf[p*SLICE], stw, t, true);

    float2* out = g_zf + (size_t)sc*WF*HH + h0;
    for (int i = tid; i < WF*16; i += 512) {
        int k = i >> 4, hh2 = i & 15;
        float2* Z = &buf[(hh2>>1)*SLICE];
        int m = (256 - k) & 255;
        float2 zk = Z[swz(k)], zm = Z[swz(m)];
        float2 v;
        if ((hh2 & 1) == 0)
            v = make_float2(0.5f*(zk.x + zm.x), 0.5f*(zk.y - zm.y));  // A[k]
        else
            v = make_float2(0.5f*(zk.y + zm.y), 0.5f*(zm.x - zk.x));  // B[k]
        out[(size_t)k*HH + hh2] = v;
    }
}

// ---------------- stage B: FFT along H, wf product, channel-sum, iFFT along H ----------------
__global__ void k_colprod(){
    __shared__ float2 buf[4*SLICE];
    __shared__ float2 acc[4*256];
    __shared__ float2 stw[256];
    int tid = threadIdx.x;               // 256
    int k = blockIdx.x;                  // 0..128
    int s = blockIdx.y;
    stw[tid] = g_tw[tid];
    for (int i = tid; i < 1024; i += 256) acc[i] = make_float2(0.f, 0.f);
    __syncthreads();

    int p = tid >> 6, t = tid & 63;
    float2* A = &buf[p*SLICE];

    for (int ic = 0; ic < 8; ic++) {
        int c = p + 4*ic;
        const float2* src = g_zf + ((size_t)(s*CC + c)*WF + k)*HH;
        #pragma unroll
        for (int m = 0; m < 4; m++) A[swz(t + 64*m)] = src[t + 64*m];
        __syncthreads();
        fft256<false>(A, stw, t, true);
        const float2* wp = g_wft + ((size_t)k*CC + c)*HH;
        #pragma unroll
        for (int m = 0; m < 4; m++) {
            int hf = t + 64*m;
            float2 zv = A[swz(hf)];
            float2 wv = wp[hf];
            float2 a = acc[p*256 + hf];
            a.x += wv.x * zv.x;        // g_re = wf_re * zf_re
            a.y -= wv.y * zv.y;        // g_im = -wf_im * zf_im
            acc[p*256 + hf] = a;
        }
        __syncthreads();
    }
    {
        float2 g0 = acc[tid], g1 = acc[256 + tid], g2 = acc[512 + tid], g3 = acc[768 + tid];
        buf[swz(tid)] = make_float2(g0.x + g1.x + g2.x + g3.x,
                                    g0.y + g1.y + g2.y + g3.y);
    }
    __syncthreads();
    fft256<true>(&buf[0], stw, t, tid < 64);
    float2 v = buf[swz(tid)];
    g_ghat[((size_t)s*WF + k)*HH + tid] = make_float2(v.x*(1.f/256.f), v.y*(1.f/256.f));
}

// ---------------- stage C: irfft along W (2 rows packed) -> output ----------------
__global__ void k_irow(float* __restrict__ out){
    __shared__ float2 buf[4*SLICE];
    __shared__ float2 stw[256];
    int tid = threadIdx.x;               // 256
    int s  = blockIdx.y;
    int h0 = blockIdx.x * 8;
    stw[tid] = g_tw[tid];
    __syncthreads();

    int p = tid >> 6, t = tid & 63;
    int ha = h0 + 2*p, hb = ha + 1;
    const float2* G = g_ghat + (size_t)s*WF*HH;
    float2* A = &buf[p*SLICE];

    #pragma unroll
    for (int m = 0; m < 4; m++) {
        int kk = t + 64*m;
        int srck = (kk <= 128) ? kk : (256 - kk);
        float2 a = G[(size_t)srck*HH + ha];
        float2 b = G[(size_t)srck*HH + hb];
        if (srck == 0 || srck == 128) { a.y = 0.f; b.y = 0.f; }   // C2R drops Im of DC/Nyquist
        float2 zv;
        if (kk <= 128) zv = make_float2(a.x - b.y, a.y + b.x);    // a + i b
        else           zv = make_float2(a.x + b.y, b.x - a.y);    // conj(a) + i conj(b)
        A[swz(kk)] = zv;
    }
    __syncthreads();
    fft256<true>(A, stw, t, true);

    float* o = out + (size_t)s*HH*WW;
    #pragma unroll
    for (int m = 0; m < 4; m++) {
        int wj = t + 64*m;
        float2 zv = A[swz(wj)];
        o[(size_t)ha*WW + wj] = zv.x * (1.f/256.f);
        o[(size_t)hb*WW + wj] = zv.y * (1.f/256.f);
    }
}

extern "C" void kernel_launch(void* const* d_in, const int* in_sizes, int n_in,
                              void* d_out, int out_size){
    const float* z    = (const float*)d_in[0];
    const float* cosw = (const float*)d_in[1];
    const float* wf   = (const float*)d_in[2];
    const float* w1   = (const float*)d_in[3];
    const float* b1   = (const float*)d_in[4];
    const float* w2   = (const float*)d_in[5];
    const float* b2   = (const float*)d_in[6];
    float* out = (float*)d_out;

    cudaFuncSetAttribute(k_conv2mma, cudaFuncAttributeMaxDynamicSharedMemorySize, SMEM2_BYTES);

    k_init<<<1024, 512>>>(wf, w2);

    dim3 gc(8, 32, SS);
    k_conv1<<<gc, 256>>>(z, w1, b1);

    dim3 gm(8, 64, SS);
    k_conv2mma<<<gm, 256, SMEM2_BYTES>>>(b2, cosw);

    dim3 ga(16, SS*CC);
    k_fftrow<<<ga, 512>>>();

    dim3 gb(WF, SS);
    k_colprod<<<gb, 256>>>();

    dim3 gi(32, SS);
    k_irow<<<gi, 256>>>(out);
}

// round 7
// speedup vs baseline: 1.5767x; 1.2251x over previous
#include <cuda_runtime.h>
#include <cuda_bf16.h>
#include <math.h>
#include <stdint.h>

#define SS   64
#define CC   32
#define CIN  3
#define HH   256
#define WW   256
#define WF   129
#define SLC  274   // per-group slice stride in float2 (2192B, 16B-aligned)

// ---------------- device scratch ----------------
__device__ __nv_bfloat16 g_x1h[(size_t)SS*HH*WW*CC];   // conv1 out hi split, [s][h][w][c]
__device__ __nv_bfloat16 g_x1l[(size_t)SS*HH*WW*CC];   // conv1 out lo split
__device__ float  g_x2[(size_t)SS*CC*HH*WW];           // conv2+LRN+coswin, [s][c][h][w]
__device__ float2 g_zf[(size_t)SS*CC*WF*HH];           // row-rfft, [s][c][k][h]
__device__ float2 g_ghat[(size_t)SS*WF*HH];            // after ifft along H, [s][k][h]
__device__ float2 g_wft[(size_t)WF*CC*HH];             // wf transposed [k][c][hf]
__device__ float2 g_tw[256];                           // e^{-2pi i m/256}
__device__ __nv_bfloat16 g_w2b[2*288*32];              // [split][k=tap*32+ci][co] bf16

__device__ __forceinline__ uint32_t smem_u32(const void* p) {
    uint32_t a;
    asm("{ .reg .u64 t; cvta.to.shared.u64 t, %1; cvt.u32.u64 %0, t; }" : "=r"(a) : "l"(p));
    return a;
}

__device__ __forceinline__ void ldsm_x4(uint32_t* r, uint32_t addr){
    asm volatile("ldmatrix.sync.aligned.m8n8.x4.shared.b16 {%0,%1,%2,%3}, [%4];"
        : "=r"(r[0]),"=r"(r[1]),"=r"(r[2]),"=r"(r[3]) : "r"(addr));
}
__device__ __forceinline__ void ldsm_x4t(uint32_t* r, uint32_t addr){
    asm volatile("ldmatrix.sync.aligned.m8n8.x4.trans.shared.b16 {%0,%1,%2,%3}, [%4];"
        : "=r"(r[0]),"=r"(r[1]),"=r"(r[2]),"=r"(r[3]) : "r"(addr));
}
__device__ __forceinline__ void mma16816(float* d, const uint32_t* a, const uint32_t* b){
    asm volatile("mma.sync.aligned.m16n8k16.row.col.f32.bf16.bf16.f32 "
        "{%0,%1,%2,%3}, {%4,%5,%6,%7}, {%8,%9}, {%0,%1,%2,%3};"
        : "+f"(d[0]), "+f"(d[1]), "+f"(d[2]), "+f"(d[3])
        : "r"(a[0]), "r"(a[1]), "r"(a[2]), "r"(a[3]), "r"(b[0]), "r"(b[1]));
}

// ================= register FFT-256 (16 threads x 16 values) =================
// Input:  thread t holds v[j] = x[16*j + t]
// Output: thread t holds X[16*j + t] in v[j]   (self-sorting)
template<bool INV>
__device__ __forceinline__ void dft16(float2* v){
    constexpr float C1 = 0.923879532511286756f;
    constexpr float S1 = 0.382683432365089772f;
    constexpr float R2 = 0.707106781186547524f;
    const float WR[10] = {1.f,  C1,  R2,  S1, 0.f, -S1, -R2, -C1, -1.f, -C1};
    const float WI[10] = {0.f, -S1, -R2, -C1, -1.f, -C1, -R2, -S1, 0.f,  S1};
    float2 c[16];
    #pragma unroll
    for (int r = 0; r < 4; r++){
        float2 a0=v[r], a1=v[r+4], a2=v[r+8], a3=v[r+12];
        float2 t0=make_float2(a0.x+a2.x, a0.y+a2.y);
        float2 t1=make_float2(a0.x-a2.x, a0.y-a2.y);
        float2 t2=make_float2(a1.x+a3.x, a1.y+a3.y);
        float2 t3=make_float2(a1.x-a3.x, a1.y-a3.y);
        float2 j3 = INV ? make_float2(-t3.y, t3.x) : make_float2(t3.y, -t3.x);
        c[r]    = make_float2(t0.x+t2.x, t0.y+t2.y);
        c[4+r]  = make_float2(t1.x+j3.x, t1.y+j3.y);
        c[8+r]  = make_float2(t0.x-t2.x, t0.y-t2.y);
        c[12+r] = make_float2(t1.x-j3.x, t1.y-j3.y);
    }
    #pragma unroll
    for (int q = 0; q < 4; q++){
        float2 b0 = c[q*4+0], b1, b2, b3;
        {   int e = q;   float cr=WR[e], ci = INV ? -WI[e] : WI[e];
            float2 a=c[q*4+1]; b1=make_float2(a.x*cr-a.y*ci, a.x*ci+a.y*cr); }
        {   int e = 2*q; float cr=WR[e], ci = INV ? -WI[e] : WI[e];
            float2 a=c[q*4+2]; b2=make_float2(a.x*cr-a.y*ci, a.x*ci+a.y*cr); }
        {   int e = 3*q; float cr=WR[e], ci = INV ? -WI[e] : WI[e];
            float2 a=c[q*4+3]; b3=make_float2(a.x*cr-a.y*ci, a.x*ci+a.y*cr); }
        float2 t0=make_float2(b0.x+b2.x, b0.y+b2.y);
        float2 t1=make_float2(b0.x-b2.x, b0.y-b2.y);
        float2 t2=make_float2(b1.x+b3.x, b1.y+b3.y);
        float2 t3=make_float2(b1.x-b3.x, b1.y-b3.y);
        float2 j3 = INV ? make_float2(-t3.y, t3.x) : make_float2(t3.y, -t3.x);
        v[q]    = make_float2(t0.x+t2.x, t0.y+t2.y);
        v[q+4]  = make_float2(t1.x+j3.x, t1.y+j3.y);
        v[q+8]  = make_float2(t0.x-t2.x, t0.y-t2.y);
        v[q+12] = make_float2(t1.x-j3.x, t1.y-j3.y);
    }
}

// slice: per-group float2[SLC] scratch (16x17 transpose), group = half-warp.
template<bool INV>
__device__ __forceinline__ void fft256r(float2* v, float2* slice, int t){
    dft16<INV>(v);
    float2 base = g_tw[t];
    if (INV) base.y = -base.y;
    float2 cur = base;
    #pragma unroll
    for (int k1 = 1; k1 < 16; k1++){
        float2 a = v[k1];
        v[k1] = make_float2(a.x*cur.x - a.y*cur.y, a.x*cur.y + a.y*cur.x);
        if (k1 < 15)
            cur = make_float2(cur.x*base.x - cur.y*base.y, cur.x*base.y + cur.y*base.x);
    }
    __syncwarp();   // guard: prior reads of slice by group mates complete
    #pragma unroll
    for (int k1 = 0; k1 < 16; k1++) slice[k1*17 + t] = v[k1];
    __syncwarp();
    #pragma unroll
    for (int n2 = 0; n2 < 16; n2++) v[n2] = slice[t*17 + n2];
    dft16<INV>(v);
}

// ---------------- init: twiddles + wf transpose + split weights ----------------
__global__ void k_init(const float* __restrict__ wf, const float* __restrict__ w2){
    int tid = blockIdx.x * blockDim.x + threadIdx.x;
    int stride = gridDim.x * blockDim.x;
    if (tid < 256) {
        double ang = -6.283185307179586476925286766559 * (double)tid / 256.0;
        g_tw[tid] = make_float2((float)cos(ang), (float)sin(ang));
    }
    for (int i = tid; i < 2*288*32; i += stride) {
        int sp = i / 9216;
        int r  = i % 9216;
        int k  = r >> 5, co = r & 31;
        int tap = k >> 5, ci = k & 31;
        int kh = tap / 3, kw = tap % 3;
        float f = w2[((co*32 + ci)*3 + kh)*3 + kw];
        __nv_bfloat16 hi = __float2bfloat16(f);
        g_w2b[i] = (sp == 0) ? hi : __float2bfloat16(f - __bfloat162float(hi));
    }
    int total = WF*CC*HH;
    for (int i = tid; i < total; i += stride) {
        int hf = i & 255;
        int c  = (i >> 8) & 31;
        int k  = i >> 13;
        const float* p = wf + (((size_t)c*HH + hf)*WF + k)*2;
        g_wft[i] = make_float2(p[0], p[1]);
    }
}

// ---------------- conv1 + relu -> split bf16, [s][h][w][c] ----------------
__global__ void k_conv1(const float* __restrict__ z, const float* __restrict__ w1,
                        const float* __restrict__ b1){
    __shared__ float sIn[3*10*34];
    __shared__ float sW[27*32];
    int s  = blockIdx.z;
    int w0 = blockIdx.x * 32, h0 = blockIdx.y * 8;
    int tid = threadIdx.x;

    for (int i = tid; i < 27*32; i += 256)
        sW[i] = w1[(size_t)(i & 31)*27 + (i >> 5)];
    for (int i = tid; i < 3*10*34; i += 256) {
        int ci = i / 340, rem = i % 340, rr = rem / 34, cc = rem % 34;
        int gh = h0 + rr - 1, gw = w0 + cc - 1;
        float v = 0.f;
        if (gh >= 0 && gh < HH && gw >= 0 && gw < WW)
            v = z[(((size_t)s*CIN + ci)*HH + gh)*WW + gw];
        sIn[i] = v;
    }
    __syncthreads();

    int wg = tid & 7, r = (tid >> 3) & 7, cob = tid >> 6;
    int co0 = cob * 8;
    float acc[4][8];
    #pragma unroll
    for (int i = 0; i < 4; i++)
        #pragma unroll
        for (int j = 0; j < 8; j++) acc[i][j] = b1[co0 + j];

    #pragma unroll
    for (int ci = 0; ci < 3; ci++)
      #pragma unroll
      for (int kh = 0; kh < 3; kh++) {
        const float* rowp = &sIn[(ci*10 + r + kh)*34];
        #pragma unroll
        for (int kw = 0; kw < 3; kw++) {
            float x0 = rowp[wg      + kw];
            float x1 = rowp[wg + 8  + kw];
            float x2 = rowp[wg + 16 + kw];
            float x3 = rowp[wg + 24 + kw];
            const float* wp = &sW[((ci*3 + kh)*3 + kw)*32 + co0];
            #pragma unroll
            for (int j = 0; j < 8; j++) {
                float wv = wp[j];
                acc[0][j] += x0*wv; acc[1][j] += x1*wv;
                acc[2][j] += x2*wv; acc[3][j] += x3*wv;
            }
        }
      }

    int hh = h0 + r;
    #pragma unroll
    for (int i = 0; i < 4; i++) {
        int ww = w0 + wg + 8*i;
        size_t base = (((size_t)s*HH + hh)*WW + ww)*CC + co0;
        #pragma unroll
        for (int j = 0; j < 8; j++) {
            float v = acc[i][j];
            v = v > 0.f ? v : 0.f;
            __nv_bfloat16 hi = __float2bfloat16(v);
            g_x1h[base + j] = hi;
            g_x1l[base + j] = __float2bfloat16(v - __bfloat162float(hi));
        }
    }
}

// ---------------- conv2 via mma.sync bf16 (3-product split, K split over 2 warpgroups) ----------------
#define RAWH_OFF 36864u
#define RAWL_OFF 49920u
#define OUT_OFF  62976u
#define BIAS_OFF 79360u
#define SMEM2_BYTES 79488

__global__ void __launch_bounds__(256, 2)
k_conv2mma(const float* __restrict__ b2, const float* __restrict__ coswin){
    extern __shared__ __align__(16) uint8_t smem[];
    uint32_t sb = smem_u32(smem);
    float* sOut  = (float*)(smem + OUT_OFF);
    float* sBias = (float*)(smem + BIAS_OFF);

    const int tid = threadIdx.x;
    const int wid = tid >> 5, lane = tid & 31;
    const int grp = wid >> 2;            // 0: steps 0-8, 1: steps 9-17
    const int hl  = wid & 3;             // h row within tile
    const int s  = blockIdx.z;
    const int h0 = blockIdx.y * 4, w0 = blockIdx.x * 32;

    if (tid < 32) sBias[tid] = b2[tid];

    const uint4* wsrc = (const uint4*)g_w2b;
    for (int u = tid; u < 2304; u += 256) {
        int sp = (u >= 1152) ? 1 : 0;
        int r  = u - sp*1152;
        int k  = r >> 2, nc = r & 3;
        uint32_t p = (uint32_t)(k*4 + (nc ^ ((k>>1)&3)));
        *(uint4*)(smem + sp*18432 + p*16) = wsrc[u];
    }

    for (int u = tid; u < 816; u += 256) {
        int rawrow = u >> 2, c = u & 3;
        int hr = rawrow / 34, wc = rawrow % 34;
        int gh = h0 - 1 + hr, gw = w0 - 1 + wc;
        uint4 vh = make_uint4(0,0,0,0), vl = make_uint4(0,0,0,0);
        if (gh >= 0 && gh < HH && gw >= 0 && gw < WW) {
            size_t gi = ((size_t)((s*HH + gh))*WW + gw)*4 + c;
            vh = ((const uint4*)g_x1h)[gi];
            vl = ((const uint4*)g_x1l)[gi];
        }
        uint32_t p = (uint32_t)(rawrow*4 + (c ^ ((rawrow>>1)&3)));
        *(uint4*)(smem + RAWH_OFF + p*16) = vh;
        *(uint4*)(smem + RAWL_OFF + p*16) = vl;
    }
    __syncthreads();

    const int t15 = lane & 15;
    const int tHi = lane >> 4;
    const int swb = (t15 >> 1) & 3;

    uint32_t bA[2][2];
    #pragma unroll
    for (int sp = 0; sp < 2; sp++)
        #pragma unroll
        for (int nbx = 0; nbx < 2; nbx++)
            bA[sp][nbx] = sb + (uint32_t)sp*18432u
                        + (uint32_t)((t15*4 + ((nbx*2 + tHi) ^ swb))*16);

    float d[2][4][4];
    #pragma unroll
    for (int mb = 0; mb < 2; mb++)
        #pragma unroll
        for (int j = 0; j < 4; j++)
            #pragma unroll
            for (int e = 0; e < 4; e++) d[mb][j][e] = 0.f;

    #pragma unroll
    for (int i = 0; i < 9; i++) {
        const int st  = grp*9 + i;
        const int tap = st >> 1, kh = tap/3, kw = tap - kh*3;
        const int c0  = (st & 1) * 2;

        uint32_t ah[2][4], al[2][4];
        #pragma unroll
        for (int mb = 0; mb < 2; mb++) {
            int rawrow = (hl + kh)*34 + kw + mb*16 + t15;
            int cc = c0 + tHi;
            uint32_t p = (uint32_t)(rawrow*4 + (cc ^ ((rawrow>>1)&3)));
            ldsm_x4(ah[mb], sb + RAWH_OFF + p*16);
            ldsm_x4(al[mb], sb + RAWL_OFF + p*16);
        }
        uint32_t wh[8], wl[8];
        ldsm_x4t(wh,     bA[0][0] + (uint32_t)st*1024u);
        ldsm_x4t(wh + 4, bA[0][1] + (uint32_t)st*1024u);
        ldsm_x4t(wl,     bA[1][0] + (uint32_t)st*1024u);
        ldsm_x4t(wl + 4, bA[1][1] + (uint32_t)st*1024u);

        #pragma unroll
        for (int mb = 0; mb < 2; mb++)
            #pragma unroll
            for (int j = 0; j < 4; j++) {
                mma16816(d[mb][j], ah[mb], wh + 2*j);
                mma16816(d[mb][j], ah[mb], wl + 2*j);
                mma16816(d[mb][j], al[mb], wh + 2*j);
            }
    }

    if (grp == 0) {
        #pragma unroll
        for (int mb = 0; mb < 2; mb++) {
            int px = hl*32 + mb*16 + (lane >> 2);
            #pragma unroll
            for (int j = 0; j < 4; j++) {
                int co = j*8 + (lane & 3)*2;
                sOut[co*128 + px]         = d[mb][j][0] + sBias[co];
                sOut[(co+1)*128 + px]     = d[mb][j][1] + sBias[co+1];
                sOut[co*128 + px + 8]     = d[mb][j][2] + sBias[co];
                sOut[(co+1)*128 + px + 8] = d[mb][j][3] + sBias[co+1];
            }
        }
    }
    __syncthreads();
    if (grp == 1) {
        #pragma unroll
        for (int mb = 0; mb < 2; mb++) {
            int px = hl*32 + mb*16 + (lane >> 2);
            #pragma unroll
            for (int j = 0; j < 4; j++) {
                int co = j*8 + (lane & 3)*2;
                sOut[co*128 + px]         += d[mb][j][0];
                sOut[(co+1)*128 + px]     += d[mb][j][1];
                sOut[co*128 + px + 8]     += d[mb][j][2];
                sOut[(co+1)*128 + px + 8] += d[mb][j][3];
            }
        }
    }
    __syncthreads();

    if (tid < 128) {
        int px = tid;
        int hh = h0 + (px >> 5), ww = w0 + (px & 31);
        float yv[32];
        #pragma unroll
        for (int c = 0; c < 32; c++) yv[c] = sOut[c*128 + px];
        float cw = coswin[(size_t)hh*WW + ww];
        float win = yv[0]*yv[0] + yv[1]*yv[1] + yv[2]*yv[2];
        size_t obase = ((size_t)s*CC*HH + (size_t)hh)*WW + ww;
        #pragma unroll
        for (int c = 0; c < 32; c++) {
            float t = 1.0f + 2e-5f * win;
            float v = yv[c] * __powf(t, -0.75f) * cw;
            g_x2[obase + (size_t)c*HH*WW] = v;
            if (c + 3 < 32) win += yv[c+3]*yv[c+3];
            if (c - 2 >= 0) win -= yv[c-2]*yv[c-2];
        }
    }
}

// ---------------- stage A: row rfft (2 rows packed), register FFT ----------------
// 256 threads = 16 groups; group g handles rows (h0+2g, h0+2g+1). Block: 32 rows.
__global__ void __launch_bounds__(256)
k_fftrow(){
    __shared__ float2 sbuf[16*SLC];
    const int tid = threadIdx.x;
    const int g = tid >> 4, t = tid & 15;
    const int sc = blockIdx.y;
    const int h0 = blockIdx.x * 32;
    float2* slice = sbuf + g*SLC;

    // stage 2 rows into slice as floats: row a at [0..255], row b at [272..527]
    {
        const float* ra = g_x2 + (size_t)sc*HH*WW + (size_t)(h0 + 2*g)*WW;
        const float4* ra4 = (const float4*)ra;
        const float4* rb4 = (const float4*)(ra + 256);
        float* sa = (float*)slice;
        #pragma unroll
        for (int q = 0; q < 4; q++) ((float4*)sa)[q*16 + t] = ra4[q*16 + t];
        #pragma unroll
        for (int q = 0; q < 4; q++) ((float4*)(sa + 272))[q*16 + t] = rb4[q*16 + t];
        __syncwarp();
        float2 v[16];
        #pragma unroll
        for (int j = 0; j < 16; j++)
            v[j] = make_float2(sa[16*j + t], sa[272 + 16*j + t]);
        fft256r<false>(v, slice, t);
        // store Z[k] into slice[k]
        __syncwarp();
        #pragma unroll
        for (int j = 0; j < 16; j++) slice[t + 16*j] = v[j];
    }
    __syncthreads();

    // unpack + write: i -> (k, h-offset idx); h = h0 + idx, pair p = idx>>1, ab = idx&1
    float2* outp = g_zf + (size_t)sc*WF*HH;
    for (int i = tid; i < WF*32; i += 256) {
        int k = i >> 5, idx = i & 31;
        int p = idx >> 1, ab = idx & 1;
        const float2* Z = sbuf + p*SLC;
        float2 zk = Z[k];
        float2 zm = Z[(256 - k) & 255];
        float2 o;
        if (ab == 0)
            o = make_float2(0.5f*(zk.x + zm.x), 0.5f*(zk.y - zm.y));   // row a spectrum
        else
            o = make_float2(0.5f*(zk.y + zm.y), 0.5f*(zm.x - zk.x));   // row b spectrum
        outp[(size_t)k*HH + h0 + idx] = o;
    }
}

// ---------------- stage B: per-k FFT along H + wf product + channel-sum + iFFT ----------------
// 256 threads = 16 groups; group g owns k = bx*16 + g (clamped).
__global__ void __launch_bounds__(256, 2)
k_colprod(){
    __shared__ float2 sbuf[16*SLC];
    const int tid = threadIdx.x;
    const int g = tid >> 4, t = tid & 15;
    const int s = blockIdx.y;
    const int k = blockIdx.x * 16 + g;
    const int kc = k <= 128 ? k : 128;
    float2* slice = sbuf + g*SLC;

    float2 facc[16];
    #pragma unroll
    for (int j = 0; j < 16; j++) facc[j] = make_float2(0.f, 0.f);

    for (int c = 0; c < 32; c++) {
        const float2* base = g_zf + ((size_t)(s*CC + c)*WF + kc)*HH;
        // stage 256 float2 into slice, then gather strided
        const float4* b4 = (const float4*)base;
        __syncwarp();
        #pragma unroll
        for (int q = 0; q < 8; q++) ((float4*)slice)[q*16 + t] = b4[q*16 + t];
        __syncwarp();
        float2 v[16];
        #pragma unroll
        for (int j = 0; j < 16; j++) v[j] = slice[16*j + t];
        fft256r<false>(v, slice, t);
        const float2* wp = g_wft + ((size_t)kc*CC + c)*HH;
        #pragma unroll
        for (int j = 0; j < 16; j++) {
            float2 wv = wp[t + 16*j];
            facc[j].x += wv.x * v[j].x;    // g_re = wf_re * zf_re
            facc[j].y -= wv.y * v[j].y;    // g_im = -wf_im * zf_im
        }
    }

    fft256r<true>(facc, slice, t);
    if (k <= 128) {
        float2* outp = g_ghat + ((size_t)s*WF + k)*HH;
        #pragma unroll
        for (int j = 0; j < 16; j++)
            outp[t + 16*j] = make_float2(facc[j].x*(1.f/256.f), facc[j].y*(1.f/256.f));
    }
}

// ---------------- stage C: irfft along W (2 rows packed), register FFT ----------------
// 256 threads = 16 groups; group g handles rows (h0+2g, h0+2g+1).
__global__ void __launch_bounds__(256)
k_irow(float* __restrict__ out){
    __shared__ float2 sbuf[16*SLC];
    const int tid = threadIdx.x;
    const int g = tid >> 4, t = tid & 15;
    const int s = blockIdx.y;
    const int h0 = blockIdx.x * 32;
    const int ha = h0 + 2*g, hb = ha + 1;
    float2* slice = sbuf + g*SLC;

    const float2* G = g_ghat + (size_t)s*WF*HH;
    float2 v[16];
    #pragma unroll
    for (int j = 0; j < 16; j++) {
        int kk = 16*j + t;
        int srck = (kk <= 128) ? kk : (256 - kk);
        float2 a = G[(size_t)srck*HH + ha];
        float2 b = G[(size_t)srck*HH + hb];
        if (srck == 0 || srck == 128) { a.y = 0.f; b.y = 0.f; }   // C2R drops Im of DC/Nyquist
        if (kk <= 128) v[j] = make_float2(a.x - b.y, a.y + b.x);  // a + i b
        else           v[j] = make_float2(a.x + b.y, b.x - a.y);  // conj(a) + i conj(b)
    }
    fft256r<true>(v, slice, t);

    float* o = out + (size_t)s*HH*WW;
    #pragma unroll
    for (int j = 0; j < 16; j++) {
        int wj = t + 16*j;
        o[(size_t)ha*WW + wj] = v[j].x * (1.f/256.f);
        o[(size_t)hb*WW + wj] = v[j].y * (1.f/256.f);
    }
}

extern "C" void kernel_launch(void* const* d_in, const int* in_sizes, int n_in,
                              void* d_out, int out_size){
    const float* z    = (const float*)d_in[0];
    const float* cosw = (const float*)d_in[1];
    const float* wf   = (const float*)d_in[2];
    const float* w1   = (const float*)d_in[3];
    const float* b1   = (const float*)d_in[4];
    const float* w2   = (const float*)d_in[5];
    const float* b2   = (const float*)d_in[6];
    float* out = (float*)d_out;

    cudaFuncSetAttribute(k_conv2mma, cudaFuncAttributeMaxDynamicSharedMemorySize, SMEM2_BYTES);

    k_init<<<1024, 512>>>(wf, w2);

    dim3 gc(8, 32, SS);
    k_conv1<<<gc, 256>>>(z, w1, b1);

    dim3 gm(8, 64, SS);
    k_conv2mma<<<gm, 256, SMEM2_BYTES>>>(b2, cosw);

    dim3 ga(8, SS*CC);
    k_fftrow<<<ga, 256>>>();

    dim3 gb(9, SS);
    k_colprod<<<gb, 256>>>();

    dim3 gi(8, SS);
    k_irow<<<gi, 256>>>(out);
}